// round 3
// baseline (speedup 1.0000x reference)
#include <cuda_runtime.h>
#include <math.h>

#define BATCH 8
#define TLEN 4096
#define DK 16
#define DV 64
// sigmoid(w - d) underflows to exactly 0.0f in fp32 for d >= 160 -> band is EXACT.
#define WIN 160
#define TQ 128                  // queries per CTA
#define KW (TQ + WIN)           // 288 key rows per CTA
#define KS 16                   // K smem row stride (floats): inner loads conflict-free
#define VS 68                   // V smem row stride (floats)
#define NTHREADS 512            // 4 lanes per query (d_v quarters)

__global__ __launch_bounds__(NTHREADS, 2)
void screening_kernel(const float* __restrict__ qg,
                      const float* __restrict__ kg,
                      const float* __restrict__ vg,
                      const float* __restrict__ s_r,
                      const float* __restrict__ s_w,
                      float* __restrict__ out)
{
    extern __shared__ float sm[];
    float* sig_sm = sm;                      // [WIN]
    float* k_sm   = sm + WIN;                // [KW * KS]
    float* v_sm   = k_sm + KW * KS;          // [KW * VS]

    const int tid     = threadIdx.x;
    const int quarter = tid & 3;             // which 16 of the 64 V columns
    const int qi      = tid >> 2;            // query within tile (0..127)
    const int qt      = blockIdx.x;
    const int b       = blockIdx.y;
    const int q0      = qt * TQ;
    const int kstart  = q0 - (WIN - 1);

    const float r = expf(s_r[0]) + 1.0f;
    const float w = expf(s_w[0]) + 1.0f;

    if (tid < WIN) {
        float x = w - (float)tid;
        sig_sm[tid] = 1.0f / (1.0f + expf(-x));
    }

    // ---- Load + L2-normalize K window: one thread per row ----
    if (tid < KW) {
        const int row = tid;
        const int j = kstart + row;
        float4 a0, a1, a2, a3;
        if (j >= 0) {
            const float4* gp = reinterpret_cast<const float4*>(kg + ((size_t)b * TLEN + j) * DK);
            a0 = gp[0]; a1 = gp[1]; a2 = gp[2]; a3 = gp[3];
        } else {
            a0 = a1 = a2 = a3 = make_float4(0.f, 0.f, 0.f, 0.f);
        }
        float ss = a0.x*a0.x + a0.y*a0.y + a0.z*a0.z + a0.w*a0.w
                 + a1.x*a1.x + a1.y*a1.y + a1.z*a1.z + a1.w*a1.w
                 + a2.x*a2.x + a2.y*a2.y + a2.z*a2.z + a2.w*a2.w
                 + a3.x*a3.x + a3.y*a3.y + a3.z*a3.z + a3.w*a3.w;
        const float inv = 1.0f / fmaxf(sqrtf(ss), 1e-12f);
        float4* dst = reinterpret_cast<float4*>(k_sm + row * KS);
        dst[0] = make_float4(a0.x*inv, a0.y*inv, a0.z*inv, a0.w*inv);
        dst[1] = make_float4(a1.x*inv, a1.y*inv, a1.z*inv, a1.w*inv);
        dst[2] = make_float4(a2.x*inv, a2.y*inv, a2.z*inv, a2.w*inv);
        dst[3] = make_float4(a3.x*inv, a3.y*inv, a3.z*inv, a3.w*inv);
    }

    // ---- Load + L2-normalize V window: 16-lane groups, one float4 per lane ----
    {
        const int g = tid >> 4;              // 32 groups
        const int l = tid & 15;
        #pragma unroll
        for (int it = 0; it < KW / 32; ++it) {   // 9 uniform iters
            const int row = g + it * 32;
            const int j = kstart + row;
            float4 x = make_float4(0.f, 0.f, 0.f, 0.f);
            if (j >= 0)
                x = reinterpret_cast<const float4*>(vg + ((size_t)b * TLEN + j) * DV)[l];
            float ss = x.x*x.x + x.y*x.y + x.z*x.z + x.w*x.w;
            #pragma unroll
            for (int m = 8; m >= 1; m >>= 1)
                ss += __shfl_xor_sync(0xffffffffu, ss, m);
            const float inv = 1.0f / fmaxf(sqrtf(ss), 1e-12f);
            float4* dst = reinterpret_cast<float4*>(v_sm + row * VS + l * 4);
            *dst = make_float4(x.x*inv, x.y*inv, x.z*inv, x.w*inv);
        }
    }

    __syncthreads();

    // ---- Query quarter: this lane holds dims [quarter*4, quarter*4+4) ----
    const int i = q0 + qi;
    float4 qv = reinterpret_cast<const float4*>(qg + ((size_t)b * TLEN + i) * DK)[quarter];
    {
        float ss = qv.x*qv.x + qv.y*qv.y + qv.z*qv.z + qv.w*qv.w;
        ss += __shfl_xor_sync(0xffffffffu, ss, 1);
        ss += __shfl_xor_sync(0xffffffffu, ss, 2);
        const float inv = 1.0f / fmaxf(sqrtf(ss), 1e-12f);
        qv.x *= inv; qv.y *= inv; qv.z *= inv; qv.w *= inv;
    }

    float acc[16];
    #pragma unroll
    for (int c = 0; c < 16; ++c) acc[c] = 0.0f;

    const float one_minus_r = 1.0f - r;
    const int dmax = (i < WIN - 1) ? i : (WIN - 1);

    #pragma unroll 2
    for (int d = 0; d <= dmax; ++d) {
        const int jj = qi + (WIN - 1) - d;           // smem row of key j = i - d
        const float4 kq = *reinterpret_cast<const float4*>(k_sm + jj * KS + quarter * 4);
        float s = qv.x * kq.x;
        s = fmaf(qv.y, kq.y, s);
        s = fmaf(qv.z, kq.z, s);
        s = fmaf(qv.w, kq.w, s);
        s += __shfl_xor_sync(0xffffffffu, s, 1);
        s += __shfl_xor_sync(0xffffffffu, s, 2);     // full dot in all 4 lanes
        float a = fmaxf(fmaf(r, s, one_minus_r), 0.0f);
        const float al = a * a * sig_sm[d];
        if (al != 0.0f) {                            // taken ~28% of warp-steps
            const float4* vr = reinterpret_cast<const float4*>(v_sm + jj * VS + quarter * 16);
            #pragma unroll
            for (int c4 = 0; c4 < 4; ++c4) {
                float4 vv = vr[c4];
                acc[4*c4+0] = fmaf(al, vv.x, acc[4*c4+0]);
                acc[4*c4+1] = fmaf(al, vv.y, acc[4*c4+1]);
                acc[4*c4+2] = fmaf(al, vv.z, acc[4*c4+2]);
                acc[4*c4+3] = fmaf(al, vv.w, acc[4*c4+3]);
            }
        }
    }

    // ---- TanhNorm epilogue (norm over all 64 via width-4 shfl reduce) ----
    float ss = 0.0f;
    #pragma unroll
    for (int c = 0; c < 16; ++c) ss = fmaf(acc[c], acc[c], ss);
    ss += __shfl_xor_sync(0xffffffffu, ss, 1);
    ss += __shfl_xor_sync(0xffffffffu, ss, 2);
    const float hn = fmaxf(sqrtf(ss), 1e-8f);
    const float scale = tanhf(hn) / hn;

    float4* op = reinterpret_cast<float4*>(out + ((size_t)b * TLEN + i) * DV + quarter * 16);
    #pragma unroll
    for (int c4 = 0; c4 < 4; ++c4)
        op[c4] = make_float4(acc[4*c4+0]*scale, acc[4*c4+1]*scale,
                             acc[4*c4+2]*scale, acc[4*c4+3]*scale);
}

extern "C" void kernel_launch(void* const* d_in, const int* in_sizes, int n_in,
                              void* d_out, int out_size)
{
    const float* q   = (const float*)d_in[0];
    const float* k   = (const float*)d_in[1];
    const float* v   = (const float*)d_in[2];
    const float* s_r = (const float*)d_in[3];
    const float* s_w = (const float*)d_in[4];
    float* out = (float*)d_out;

    const size_t smem = (size_t)(WIN + KW * KS + KW * VS) * sizeof(float); // ~97.4 KB
    cudaFuncSetAttribute(screening_kernel, cudaFuncAttributeMaxDynamicSharedMemorySize, (int)smem);

    dim3 grid(TLEN / TQ, BATCH);
    screening_kernel<<<grid, NTHREADS, smem>>>(q, k, v, s_r, s_w, out);
}